// round 1
// baseline (speedup 1.0000x reference)
#include <cuda_runtime.h>
#include <cstdint>

// ----------------------------------------------------------------------------
// Bidirectional 6-layer GRU, SEQ=512, B=10, H=256, I=128.
// Key insight: only fwd_out[..., :128] feeds the next layer, so bwd scans of
// layers 0-4 are dead. 7 scan units total: fwd L0..L5 (units 0..5) + bwd L5
// (unit 6). Units pipeline with lag-1 through global memory + release/acquire
// flags. Each unit = 16 persistent CTAs, each owning 16 hidden units for all
// 10 batches, weights SMEM-resident, fp32x2 packed FMA for the dot products.
// ----------------------------------------------------------------------------

#define HID    256
#define SEQ    512
#define BATCH  10
#define NUNITS 7
#define NSLICE 16
#define JPER   16          // hidden units per CTA
#define NTHREADS 256
#define KTOT   384         // 128 (x) + 256 (h)
#define K2TOT  192

// fwd hidden outputs for layers 0..4 (layer5/bwd5 write straight into d_out)
__device__ float g_out[5][SEQ][BATCH][HID];
__device__ int   g_flag[NUNITS][NSLICE];

__device__ __forceinline__ int ld_acquire(const int* p) {
    int v;
    asm volatile("ld.acquire.gpu.b32 %0, [%1];" : "=r"(v) : "l"(p) : "memory");
    return v;
}
__device__ __forceinline__ void st_release(int* p, int v) {
    asm volatile("st.release.gpu.b32 [%0], %1;" :: "l"(p), "r"(v) : "memory");
}
// packed 2xfp32 FMA (Blackwell f32x2 pipe: 2x throughput vs 3-reg FFMA)
__device__ __forceinline__ void ffma2(unsigned long long& d,
                                      unsigned long long a,
                                      unsigned long long b) {
    asm volatile("fma.rn.f32x2 %0, %1, %2, %0;" : "+l"(d) : "l"(a), "l"(b));
}
__device__ __forceinline__ float2 u2f2(unsigned long long u) {
    float2 f;
    asm("mov.b64 {%0, %1}, %2;" : "=f"(f.x), "=f"(f.y) : "l"(u));
    return f;
}
__device__ __forceinline__ float sigmoidf_fast(float x) {
    return 1.0f / (1.0f + __expf(-x));
}

extern "C" __global__ void __launch_bounds__(NTHREADS, 1)
gru_persistent_kernel(const float* __restrict__ x,
                      const float* __restrict__ w_ih_l0,
                      const float* __restrict__ w_ih_rest,
                      const float* __restrict__ w_hh,
                      float* __restrict__ out)
{
    const int u     = blockIdx.x / NSLICE;   // scan unit 0..6
    const int slice = blockIdx.x % NSLICE;   // 16-hidden-unit slice
    const int j0    = slice * JPER;
    const int tid   = threadIdx.x;
    const int layer = (u < 6) ? u : 5;
    const int dir   = (u == 6) ? 1 : 0;

    extern __shared__ char smem[];
    float2* ws2  = (float2*)smem;                                  // [192][3][16] f2 = 73728 B
    unsigned long long* ws2u = (unsigned long long*)smem;
    float*  xh   = (float*)(smem + 73728);                         // [10][384]     = 15360 B
    unsigned long long* xh2u = (unsigned long long*)(smem + 73728);
    float4* parts = (float4*)(smem + 73728 + 15360);               // [8][10][16]   = 20480 B

    // -------- load weights into SMEM: layout ws2[k2][slot(r,z,n)][jj] --------
    // k<128 -> W_ih column k ; k>=128 -> W_hh column k-128
    const float* Whh = w_hh + (size_t)(layer * 2 + dir) * 768 * 256;
    const float* Wih;
    int pitch;
    if (layer == 0) { Wih = w_ih_l0 + (size_t)dir * 768 * 128; pitch = 128; }
    else            { Wih = w_ih_rest + (size_t)((layer - 1) * 2 + dir) * 768 * 512; pitch = 512; }

    for (int idx = tid; idx < K2TOT * 3 * JPER; idx += NTHREADS) {
        int jj   = idx & 15;
        int slot = (idx >> 4) % 3;
        int k2   = idx / 48;
        int row  = slot * 256 + j0 + jj;
        int k    = k2 * 2;
        float2 v;
        if (k < 128) {
            v.x = Wih[(size_t)row * pitch + k];
            v.y = Wih[(size_t)row * pitch + k + 1];
        } else {
            v.x = Whh[(size_t)row * 256 + (k - 128)];
            v.y = Whh[(size_t)row * 256 + (k - 127)];
        }
        ws2[idx] = v;
    }
    __syncthreads();

    const int w     = tid >> 5;       // warp id 0..7 (split-K)
    const int lane  = tid & 31;
    const int jj    = lane & 15;      // hidden unit within slice
    const int half  = lane >> 4;      // batch group: 0 -> b0..4, 1 -> b5..9
    const int bbase = half * 5;

    for (int s = 0; s < SEQ; ++s) {
        // ---- 1. wait on dependencies ----
        if (s > 0 && tid < NSLICE) {
            const int* fp = &g_flag[u][tid];
            while (ld_acquire(fp) < s) __nanosleep(64);
        }
        if (u >= 1 && tid >= 16 && tid < 24) {
            int src_u = (u == 6) ? 4 : (u - 1);
            int tgt   = (u == 6) ? (SEQ - s) : (s + 1);
            const int* fp = &g_flag[src_u][tid - 16];
            while (ld_acquire(fp) < tgt) __nanosleep(64);
        }
        __syncthreads();

        // ---- 2. stage xh = [x(128) | h_prev(256)] per batch into SMEM ----
        if (u == 0) {
            const float4* src = (const float4*)(x + (size_t)s * BATCH * 128);
            for (int idx = tid; idx < 320; idx += NTHREADS) {
                int b = idx >> 5, q = idx & 31;
                *(float4*)&xh[b * KTOT + q * 4] = src[idx];
            }
        } else {
            int src_u = (u == 6) ? 4 : (u - 1);
            int ss    = (u == 6) ? (SEQ - 1 - s) : s;
            const float* src = &g_out[src_u][ss][0][0];
            for (int idx = tid; idx < 320; idx += NTHREADS) {
                int b = idx >> 5, q = idx & 31;
                *(float4*)&xh[b * KTOT + q * 4] = *(const float4*)&src[b * HID + q * 4];
            }
        }
        for (int idx = tid; idx < 640; idx += NTHREADS) {
            int b = idx >> 6, q = idx & 63;
            float4 v = make_float4(0.f, 0.f, 0.f, 0.f);
            if (s > 0) {
                if (u < 5)       v = *(const float4*)&g_out[u][s - 1][b][q * 4];
                else if (u == 5) v = *(const float4*)&out[((size_t)(s - 1) * BATCH + b) * 512 + q * 4];
                else             v = *(const float4*)&out[((size_t)(s - 1) * BATCH + b) * 512 + 256 + q * 4];
            }
            *(float4*)&xh[b * KTOT + 128 + q * 4] = v;
        }
        __syncthreads();

        // ---- 3. split-K partial dot products (f32x2 packed FMA) ----
        // gates r,z accumulate over full k; n is split: nx over x-part (k<128),
        // nh over h-part (k>=128) because n = tanh(nx + r*nh).
        unsigned long long ar[5]  = {0,0,0,0,0};
        unsigned long long az[5]  = {0,0,0,0,0};
        unsigned long long anx[5] = {0,0,0,0,0};
        unsigned long long anh[5] = {0,0,0,0,0};

        const int k2s    = w * 24;
        const int k2e    = k2s + 24;
        const int aEnd   = (k2e < 64) ? k2e : 64;   // k2=64 <=> k=128 boundary
        const int bStart = (k2s > 64) ? k2s : 64;

        #pragma unroll 2
        for (int k2 = k2s; k2 < aEnd; ++k2) {
            unsigned long long wr = ws2u[k2 * 48 + jj];
            unsigned long long wz = ws2u[k2 * 48 + 16 + jj];
            unsigned long long wn = ws2u[k2 * 48 + 32 + jj];
            #pragma unroll
            for (int i = 0; i < 5; ++i) {
                unsigned long long xv = xh2u[(bbase + i) * K2TOT + k2];
                ffma2(ar[i],  wr, xv);
                ffma2(az[i],  wz, xv);
                ffma2(anx[i], wn, xv);
            }
        }
        #pragma unroll 2
        for (int k2 = bStart; k2 < k2e; ++k2) {
            unsigned long long wr = ws2u[k2 * 48 + jj];
            unsigned long long wz = ws2u[k2 * 48 + 16 + jj];
            unsigned long long wn = ws2u[k2 * 48 + 32 + jj];
            #pragma unroll
            for (int i = 0; i < 5; ++i) {
                unsigned long long xv = xh2u[(bbase + i) * K2TOT + k2];
                ffma2(ar[i],  wr, xv);
                ffma2(az[i],  wz, xv);
                ffma2(anh[i], wn, xv);
            }
        }

        #pragma unroll
        for (int i = 0; i < 5; ++i) {
            int b = bbase + i;
            float2 fr  = u2f2(ar[i]);
            float2 fz  = u2f2(az[i]);
            float2 fnx = u2f2(anx[i]);
            float2 fnh = u2f2(anh[i]);
            parts[(w * BATCH + b) * JPER + jj] =
                make_float4(fr.x + fr.y, fz.x + fz.y, fnx.x + fnx.y, fnh.x + fnh.y);
        }
        __syncthreads();

        // ---- 4. reduce across 8 warps + GRU elementwise + store h ----
        if (tid < BATCH * JPER) {
            int b = tid >> 4, j = tid & 15;
            float4 a = parts[b * JPER + j];
            #pragma unroll
            for (int ww = 1; ww < 8; ++ww) {
                float4 p = parts[(ww * BATCH + b) * JPER + j];
                a.x += p.x; a.y += p.y; a.z += p.z; a.w += p.w;
            }
            float r = sigmoidf_fast(a.x);
            float z = sigmoidf_fast(a.y);
            float n = tanhf(a.z + r * a.w);
            float hp = (s > 0) ? xh[b * KTOT + 128 + j0 + j] : 0.0f;
            float h  = fmaf(z, hp - n, n);
            if (u < 5)       g_out[u][s][b][j0 + j] = h;
            else if (u == 5) out[((size_t)s * BATCH + b) * 512 + j0 + j] = h;
            else             out[((size_t)s * BATCH + b) * 512 + 256 + j0 + j] = h;
        }
        __syncthreads();

        // ---- 5. publish progress ----
        if (tid == 0) {
            __threadfence();
            st_release(&g_flag[u][slice], s + 1);
        }
    }
}

extern "C" __global__ void zero_flags_kernel() {
    int t = threadIdx.x;
    if (t < NUNITS * NSLICE) ((int*)g_flag)[t] = 0;
}

extern "C" void kernel_launch(void* const* d_in, const int* in_sizes, int n_in,
                              void* d_out, int out_size) {
    const float* x         = (const float*)d_in[0];
    const float* w_ih_l0   = (const float*)d_in[1];
    const float* w_ih_rest = (const float*)d_in[2];
    const float* w_hh      = (const float*)d_in[3];
    float* out = (float*)d_out;

    const int smem_bytes = 73728 + 15360 + 20480;  // 109568
    cudaFuncSetAttribute(gru_persistent_kernel,
                         cudaFuncAttributeMaxDynamicSharedMemorySize, smem_bytes);

    zero_flags_kernel<<<1, 128>>>();
    gru_persistent_kernel<<<NUNITS * NSLICE, NTHREADS, smem_bytes>>>(
        x, w_ih_l0, w_ih_rest, w_hh, out);
}

// round 2
// speedup vs baseline: 1.7991x; 1.7991x over previous
#include <cuda_runtime.h>
#include <cstdint>

// ----------------------------------------------------------------------------
// Bidirectional 6-layer GRU, SEQ=512, B=10, H=256, I=128.
// 7 live scan units (fwd L0..L5 + bwd L5). Each unit = 2 clusters of 8 CTAs
// (one per batch-group of 5). CTA owns 5 batches x 32 hidden units, full
// weights SMEM-resident (fp32). h exchanged per step via DSMEM push + cluster
// barrier (double-buffered xh). Inter-unit x handoff via global staging with
// release/acquire flags (lag-1 pipeline, latency off the steady-state path).
// ----------------------------------------------------------------------------

#define SEQ    512
#define BATCH  10
#define NTH    256

typedef unsigned long long ull;

// inter-unit staging: units 0..4 publish h[..., :128]
__device__ float g_stage[5][SEQ][BATCH][128];
__device__ int   g_flag[5][2][4][8];   // [unit][bg][producer js][pad]

// dynamic smem layout
#define WS_BYTES    (3*96*32*16)              // 147456: weights ulonglong2[g][k4][j]
#define XH_OFF      WS_BYTES
#define XH_BYTES    (2*5*384*4)               // 15360: xh[2][5][384] (x|h)
#define PARTS_OFF   (XH_OFF + XH_BYTES)
#define PARTS_BYTES (8*5*32*16)               // 20480: parts[w][b][j] float4
#define HOWN_OFF    (PARTS_OFF + PARTS_BYTES)
#define HOWN_BYTES  (5*32*4)                  // 640
#define SMEM_TOTAL  (HOWN_OFF + HOWN_BYTES)   // 183936

__device__ __forceinline__ int ld_acquire(const int* p) {
    int v;
    asm volatile("ld.acquire.gpu.b32 %0, [%1];" : "=r"(v) : "l"(p) : "memory");
    return v;
}
__device__ __forceinline__ void st_release(int* p, int v) {
    asm volatile("st.release.gpu.b32 [%0], %1;" :: "l"(p), "r"(v) : "memory");
}
__device__ __forceinline__ void ffma2(ull& d, ull a, ull b) {
    asm volatile("fma.rn.f32x2 %0, %1, %2, %0;" : "+l"(d) : "l"(a), "l"(b));
}
__device__ __forceinline__ float2 u2f2(ull u) {
    float2 f;
    asm("mov.b64 {%0, %1}, %2;" : "=f"(f.x), "=f"(f.y) : "l"(u));
    return f;
}
__device__ __forceinline__ float sigmoidf_fast(float x) {
    return 1.0f / (1.0f + __expf(-x));
}
__device__ __forceinline__ float tanhf_fast(float x) {
    return fmaf(2.0f, 1.0f / (1.0f + __expf(-2.0f * x)), -1.0f);
}
__device__ __forceinline__ uint32_t smem_u32(const void* p) {
    uint32_t a;
    asm("{ .reg .u64 t; cvta.to.shared.u64 t, %1; cvt.u32.u64 %0, t; }"
        : "=r"(a) : "l"(p));
    return a;
}
__device__ __forceinline__ void st_cluster_f4(uint32_t laddr, uint32_t rank, float4 v) {
    asm volatile(
        "{\n\t.reg .b32 ra;\n\t"
        "mapa.shared::cluster.u32 ra, %0, %1;\n\t"
        "st.shared::cluster.v4.f32 [ra], {%2, %3, %4, %5};\n\t}"
        :: "r"(laddr), "r"(rank), "f"(v.x), "f"(v.y), "f"(v.z), "f"(v.w)
        : "memory");
}
#define CLUSTER_ARRIVE() asm volatile("barrier.cluster.arrive.aligned;" ::: "memory")
#define CLUSTER_WAIT()   asm volatile("barrier.cluster.wait.aligned;"   ::: "memory")

extern "C" __global__ void __launch_bounds__(NTH, 1) __cluster_dims__(8, 1, 1)
gru_persistent_kernel(const float* __restrict__ x,
                      const float* __restrict__ w_ih_l0,
                      const float* __restrict__ w_ih_rest,
                      const float* __restrict__ w_hh,
                      float* __restrict__ out)
{
    extern __shared__ char smem[];
    ulonglong2* ws4   = (ulonglong2*)smem;           // [3][96][32]
    float*      xh    = (float*)(smem + XH_OFF);     // [2][5][384]
    float4*     parts = (float4*)(smem + PARTS_OFF); // [8][5][32]
    float*      hown  = (float*)(smem + HOWN_OFF);   // [5][32]
    float4*     hown4 = (float4*)(smem + HOWN_OFF);  // [5][8]
    const uint32_t smem_base = smem_u32(smem);

    const int cta = blockIdx.x;
    const int u   = cta >> 4;          // scan unit 0..6
    const int bg  = (cta >> 3) & 1;    // batch group (cluster = (u,bg))
    const int js  = cta & 7;           // hidden slice = cluster rank
    const int j0  = js * 32;
    const int tid = threadIdx.x;
    const int layer = (u < 6) ? u : 5;
    const int dir   = (u == 6) ? 1 : 0;
    const int src_u = (u == 6) ? 4 : (u - 1);

    // -------- weights -> smem, layout ws4[g][k4][j] = {w[k..k+1], w[k+2..k+3]} --------
    const float* Whh = w_hh + (size_t)(layer * 2 + dir) * 768 * 256;
    const float* Wih;
    int pitch;
    if (layer == 0) { Wih = w_ih_l0 + (size_t)dir * 768 * 128; pitch = 128; }
    else            { Wih = w_ih_rest + (size_t)((layer - 1) * 2 + dir) * 768 * 512; pitch = 512; }

    for (int idx = tid; idx < 3 * 96 * 32; idx += NTH) {
        int j  = idx & 31;
        int k4 = (idx >> 5) % 96;
        int g  = idx / (96 * 32);
        int row = g * 256 + j0 + j;
        int k   = k4 * 4;
        const float* src = (k < 128) ? (Wih + (size_t)row * pitch + k)
                                     : (Whh + (size_t)row * 256 + (k - 128));
        ((float4*)ws4)[idx] = *(const float4*)src;
    }
    // zero h-section of buffer 0 (h0 = 0)
    for (int t = tid; t < 320; t += NTH) {
        int b = t >> 6, q = t & 63;
        *(float4*)&xh[b * 384 + 128 + q * 4] = make_float4(0.f, 0.f, 0.f, 0.f);
    }
    __syncthreads();

    // stage x-part (128 features x 5 batches) for step sn into buffer pb
    auto stage_x = [&](int sn, int pb) {
        float* dst = xh + pb * 1920;
        if (u == 0) {
            const float* src = x + ((size_t)sn * BATCH + bg * 5) * 128;
            for (int t = tid; t < 160; t += NTH) {
                int b = t >> 5, q = t & 31;
                *(float4*)&dst[b * 384 + q * 4] = *(const float4*)&src[b * 128 + q * 4];
            }
        } else {
            int ss   = (u == 6) ? (SEQ - 1 - sn) : sn;
            int need = (u == 6) ? (SEQ - sn) : (sn + 1);
            if (tid < 4) {
                const int* fp = &g_flag[src_u][bg][tid][0];
                while (ld_acquire(fp) < need) __nanosleep(128);
            }
            __syncthreads();
            const float* src = &g_stage[src_u][ss][bg * 5][0];
            for (int t = tid; t < 160; t += NTH) {
                int b = t >> 5, q = t & 31;
                *(float4*)&dst[b * 384 + q * 4] = *(const float4*)&src[b * 128 + q * 4];
            }
        }
    };

    stage_x(0, 0);
    __syncthreads();

    const int w  = tid >> 5;
    const int jl = tid & 31;
    const int k4s = w * 12, k4e = k4s + 12;
    const int aE = (k4e < 32) ? k4e : 32;   // k4 32 <=> k=128 (x|h boundary)
    const int bS = (k4s > 32) ? k4s : 32;

    int p = 0;
    for (int s = 0; s < SEQ; ++s) {
        // ---- split-K gate partials (f32x2 packed FMA, LDS.128 everywhere) ----
        ull ar[5]  = {0,0,0,0,0};
        ull az[5]  = {0,0,0,0,0};
        ull anx[5] = {0,0,0,0,0};
        ull anh[5] = {0,0,0,0,0};
        const ulonglong2* X = (const ulonglong2*)(xh + p * 1920);  // [b][96]

        #pragma unroll 2
        for (int k4 = k4s; k4 < aE; ++k4) {
            ulonglong2 wr = ws4[k4 * 32 + jl];
            ulonglong2 wz = ws4[(96 + k4) * 32 + jl];
            ulonglong2 wn = ws4[(192 + k4) * 32 + jl];
            #pragma unroll
            for (int i = 0; i < 5; ++i) {
                ulonglong2 xv = X[i * 96 + k4];
                ffma2(ar[i],  wr.x, xv.x); ffma2(ar[i],  wr.y, xv.y);
                ffma2(az[i],  wz.x, xv.x); ffma2(az[i],  wz.y, xv.y);
                ffma2(anx[i], wn.x, xv.x); ffma2(anx[i], wn.y, xv.y);
            }
        }
        #pragma unroll 2
        for (int k4 = bS; k4 < k4e; ++k4) {
            ulonglong2 wr = ws4[k4 * 32 + jl];
            ulonglong2 wz = ws4[(96 + k4) * 32 + jl];
            ulonglong2 wn = ws4[(192 + k4) * 32 + jl];
            #pragma unroll
            for (int i = 0; i < 5; ++i) {
                ulonglong2 xv = X[i * 96 + k4];
                ffma2(ar[i],  wr.x, xv.x); ffma2(ar[i],  wr.y, xv.y);
                ffma2(az[i],  wz.x, xv.x); ffma2(az[i],  wz.y, xv.y);
                ffma2(anh[i], wn.x, xv.x); ffma2(anh[i], wn.y, xv.y);
            }
        }
        #pragma unroll
        for (int i = 0; i < 5; ++i) {
            float2 fr = u2f2(ar[i]), fz = u2f2(az[i]);
            float2 fx = u2f2(anx[i]), fh = u2f2(anh[i]);
            parts[(w * 5 + i) * 32 + jl] =
                make_float4(fr.x + fr.y, fz.x + fz.y, fx.x + fx.y, fh.x + fh.y);
        }
        __syncthreads();

        // ---- reduce 8 warps + GRU elementwise + output stores ----
        if (tid < 160) {
            int b = tid >> 5, j = tid & 31;
            float4 a = parts[b * 32 + j];
            #pragma unroll
            for (int ww = 1; ww < 8; ++ww) {
                float4 q = parts[(ww * 5 + b) * 32 + j];
                a.x += q.x; a.y += q.y; a.z += q.z; a.w += q.w;
            }
            float r = sigmoidf_fast(a.x);
            float z = sigmoidf_fast(a.y);
            float n = tanhf_fast(a.z + r * a.w);
            float hp = xh[p * 1920 + b * 384 + 128 + j0 + j];
            float h  = fmaf(z, hp - n, n);
            hown[b * 32 + j] = h;
            int bglob = bg * 5 + b;
            if (u == 5)      out[((size_t)s * BATCH + bglob) * 512 + j0 + j] = h;
            else if (u == 6) out[((size_t)s * BATCH + bglob) * 512 + 256 + j0 + j] = h;
            else if (js < 4) g_stage[u][s][bglob][j0 + j] = h;
        }
        __syncthreads();

        // ---- DSMEM push: own 32-j slice -> h-section of every peer's next buf ----
        {
            uint32_t nxt = smem_base + XH_OFF + (uint32_t)((p ^ 1) * 7680);
            for (int it = tid; it < 320; it += NTH) {
                int peer = it / 40;
                int r2   = it - peer * 40;
                int b = r2 >> 3, j4 = r2 & 7;
                float4 v = hown4[b * 8 + j4];
                uint32_t addr = nxt + (uint32_t)((b * 384 + 128 + j0 + j4 * 4) * 4);
                st_cluster_f4(addr, (uint32_t)peer, v);
            }
        }
        CLUSTER_ARRIVE();

        // ---- publish to next unit + prefetch next x (hidden behind barrier) ----
        if (u < 5 && js < 4 && tid == 0) {
            __threadfence();
            st_release(&g_flag[u][bg][js][0], s + 1);
        }
        if (s + 1 < SEQ) stage_x(s + 1, p ^ 1);
        __syncthreads();
        CLUSTER_WAIT();
        p ^= 1;
    }
}

extern "C" __global__ void zero_flags_kernel() {
    int t = threadIdx.x;
    if (t < 5 * 2 * 4 * 8) ((int*)g_flag)[t] = 0;
}

extern "C" void kernel_launch(void* const* d_in, const int* in_sizes, int n_in,
                              void* d_out, int out_size) {
    const float* x         = (const float*)d_in[0];
    const float* w_ih_l0   = (const float*)d_in[1];
    const float* w_ih_rest = (const float*)d_in[2];
    const float* w_hh      = (const float*)d_in[3];
    float* out = (float*)d_out;

    cudaFuncSetAttribute(gru_persistent_kernel,
                         cudaFuncAttributeMaxDynamicSharedMemorySize, SMEM_TOTAL);

    zero_flags_kernel<<<1, 320>>>();
    gru_persistent_kernel<<<112, NTH, SMEM_TOTAL>>>(x, w_ih_l0, w_ih_rest, w_hh, out);
}

// round 3
// speedup vs baseline: 1.9166x; 1.0653x over previous
#include <cuda_runtime.h>
#include <cstdint>

// ----------------------------------------------------------------------------
// Bidirectional 6-layer GRU, SEQ=512, B=10, H=256, I=128.
// 7 live scan units (fwd L0..L5 + bwd L5); bwd L0..L4 are dead code.
// Unit = 2 clusters of 8 CTAs (per batch-group of 5). CTA owns 5 b x 32 j,
// weights SMEM-resident fp32, f32x2 packed FMA.
// h-exchange per step: st.async (remote store + mbarrier complete_tx) -> no
// per-step cluster barrier. x-part of gate GEMV computed in the wait shadow.
// Inter-unit handoff: global staging + release/acquire flags (lag-1).
// ----------------------------------------------------------------------------

#define SEQ    512
#define BATCH  10
#define NTH    256

typedef unsigned long long ull;

__device__ float g_stage[5][SEQ][BATCH][128];
__device__ int   g_flag[5][2][4][8];

// smem layout
#define WS_BYTES    (3*96*32*16)              // 147456 weights ulonglong2[g][k4][j]
#define XH_OFF      WS_BYTES
#define XH_BYTES    (2*5*384*4)               // 15360 xh[2][5][384]
#define PARTS_OFF   (XH_OFF + XH_BYTES)
#define PARTS_BYTES (8*5*32*16)               // 20480 parts[w][b][j] float4
#define HOWN_OFF    (PARTS_OFF + PARTS_BYTES)
#define HOWN_BYTES  (5*32*4)                  // 640
#define MBAR_OFF    (HOWN_OFF + HOWN_BYTES)
#define SMEM_TOTAL  (MBAR_OFF + 16)           // 183968

#define HBYTES_PER_STEP 5120                  // 8 peers x 640 B

__device__ __forceinline__ int ld_acquire(const int* p) {
    int v;
    asm volatile("ld.acquire.gpu.b32 %0, [%1];" : "=r"(v) : "l"(p) : "memory");
    return v;
}
__device__ __forceinline__ void st_release(int* p, int v) {
    asm volatile("st.release.gpu.b32 [%0], %1;" :: "l"(p), "r"(v) : "memory");
}
__device__ __forceinline__ void ffma2(ull& d, ull a, ull b) {
    asm volatile("fma.rn.f32x2 %0, %1, %2, %0;" : "+l"(d) : "l"(a), "l"(b));
}
__device__ __forceinline__ float2 u2f2(ull u) {
    float2 f;
    asm("mov.b64 {%0, %1}, %2;" : "=f"(f.x), "=f"(f.y) : "l"(u));
    return f;
}
__device__ __forceinline__ float sigmoidf_fast(float x) {
    return 1.0f / (1.0f + __expf(-x));
}
__device__ __forceinline__ float tanhf_fast(float x) {
    return fmaf(2.0f, 1.0f / (1.0f + __expf(-2.0f * x)), -1.0f);
}
__device__ __forceinline__ uint32_t smem_u32(const void* p) {
    uint32_t a;
    asm("{ .reg .u64 t; cvta.to.shared.u64 t, %1; cvt.u32.u64 %0, t; }"
        : "=r"(a) : "l"(p));
    return a;
}
// remote store + remote mbarrier complete_tx (16 bytes), fire-and-forget
__device__ __forceinline__ void st_async_f4(uint32_t laddr, uint32_t lmbar,
                                            uint32_t rank, float4 v) {
    asm volatile(
        "{\n\t.reg .b32 ra, rm;\n\t"
        "mapa.shared::cluster.u32 ra, %0, %2;\n\t"
        "mapa.shared::cluster.u32 rm, %1, %2;\n\t"
        "st.async.shared::cluster.mbarrier::complete_tx::bytes.v4.f32 "
        "[ra], {%3, %4, %5, %6}, [rm];\n\t}"
        :: "r"(laddr), "r"(lmbar), "r"(rank),
           "f"(v.x), "f"(v.y), "f"(v.z), "f"(v.w)
        : "memory");
}
__device__ __forceinline__ void mbar_init(uint32_t mbar, uint32_t cnt) {
    asm volatile("mbarrier.init.shared.b64 [%0], %1;" :: "r"(mbar), "r"(cnt) : "memory");
}
__device__ __forceinline__ void mbar_expect_tx(uint32_t mbar, uint32_t bytes) {
    asm volatile("mbarrier.arrive.expect_tx.shared.b64 _, [%0], %1;"
                 :: "r"(mbar), "r"(bytes) : "memory");
}
__device__ __forceinline__ void mbar_wait(uint32_t mbar, uint32_t parity) {
    asm volatile(
        "{\n\t.reg .pred P;\n\t"
        "LWAIT_%=:\n\t"
        "mbarrier.try_wait.parity.acquire.cluster.shared::cta.b64 P, [%0], %1, 0x989680;\n\t"
        "@!P bra LWAIT_%=;\n\t}"
        :: "r"(mbar), "r"(parity) : "memory");
}
#define CLUSTER_SYNC() do { \
    asm volatile("barrier.cluster.arrive.aligned;" ::: "memory"); \
    asm volatile("barrier.cluster.wait.aligned;"   ::: "memory"); \
} while (0)

extern "C" __global__ void __launch_bounds__(NTH, 1) __cluster_dims__(8, 1, 1)
gru_persistent_kernel(const float* __restrict__ x,
                      const float* __restrict__ w_ih_l0,
                      const float* __restrict__ w_ih_rest,
                      const float* __restrict__ w_hh,
                      float* __restrict__ out)
{
    extern __shared__ char smem[];
    ulonglong2* ws4   = (ulonglong2*)smem;
    float*      xh    = (float*)(smem + XH_OFF);
    float4*     parts = (float4*)(smem + PARTS_OFF);
    float*      hown  = (float*)(smem + HOWN_OFF);
    float4*     hown4 = (float4*)(smem + HOWN_OFF);
    const uint32_t smem_base = smem_u32(smem);
    const uint32_t mbar_addr = smem_base + MBAR_OFF;   // mbar[0], mbar[1] 8B each

    const int cta = blockIdx.x;
    const int u   = cta >> 4;
    const int bg  = (cta >> 3) & 1;
    const int js  = cta & 7;
    const int j0  = js * 32;
    const int tid = threadIdx.x;
    const int layer = (u < 6) ? u : 5;
    const int dir   = (u == 6) ? 1 : 0;
    const int src_u = (u == 6) ? 4 : (u - 1);

    // -------- weights -> smem: ws4[g][k4][j] --------
    const float* Whh = w_hh + (size_t)(layer * 2 + dir) * 768 * 256;
    const float* Wih;
    int pitch;
    if (layer == 0) { Wih = w_ih_l0 + (size_t)dir * 768 * 128; pitch = 128; }
    else            { Wih = w_ih_rest + (size_t)((layer - 1) * 2 + dir) * 768 * 512; pitch = 512; }

    for (int idx = tid; idx < 3 * 96 * 32; idx += NTH) {
        int j  = idx & 31;
        int k4 = (idx >> 5) % 96;
        int g  = idx / (96 * 32);
        int row = g * 256 + j0 + j;
        int k   = k4 * 4;
        const float* src = (k < 128) ? (Wih + (size_t)row * pitch + k)
                                     : (Whh + (size_t)row * 256 + (k - 128));
        ((float4*)ws4)[idx] = *(const float4*)src;
    }
    // zero h-section of buffer 0
    for (int t = tid; t < 320; t += NTH) {
        int b = t >> 6, q = t & 63;
        *(float4*)&xh[b * 384 + 128 + q * 4] = make_float4(0.f, 0.f, 0.f, 0.f);
    }
    if (tid == 0) {
        mbar_init(mbar_addr, 1);
        mbar_init(mbar_addr + 8, 1);
        mbar_expect_tx(mbar_addr,     HBYTES_PER_STEP);  // first use: h(1) at s=2
        mbar_expect_tx(mbar_addr + 8, HBYTES_PER_STEP);  // first use: h(0) at s=1
    }
    __syncthreads();
    CLUSTER_SYNC();   // mbarriers initialized cluster-wide before any st.async

    auto stage_x = [&](int sn, int pb) {
        float* dst = xh + pb * 1920;
        if (u == 0) {
            const float* src = x + ((size_t)sn * BATCH + bg * 5) * 128;
            for (int t = tid; t < 160; t += NTH) {
                int b = t >> 5, q = t & 31;
                *(float4*)&dst[b * 384 + q * 4] = *(const float4*)&src[b * 128 + q * 4];
            }
        } else {
            int ss   = (u == 6) ? (SEQ - 1 - sn) : sn;
            int need = (u == 6) ? (SEQ - sn) : (sn + 1);
            if (tid < 4) {
                const int* fp = &g_flag[src_u][bg][tid][0];
                while (ld_acquire(fp) < need) __nanosleep(128);
            }
            __syncthreads();
            const float* src = &g_stage[src_u][ss][bg * 5][0];
            for (int t = tid; t < 160; t += NTH) {
                int b = t >> 5, q = t & 31;
                *(float4*)&dst[b * 384 + q * 4] = *(const float4*)&src[b * 128 + q * 4];
            }
        }
    };

    const int w  = tid >> 5;
    const int jl = tid & 31;
    const int xk4s = w * 4;        // x-part: 32 k4 over 8 warps
    const int hk4s = 32 + w * 8;   // h-part: 64 k4 over 8 warps

    // persistent x-part partials for the *next* step
    ull xr[5], xz[5], xn[5];
    auto compute_xpart = [&](int pb) {
        #pragma unroll
        for (int i = 0; i < 5; ++i) { xr[i] = 0; xz[i] = 0; xn[i] = 0; }
        const ulonglong2* X = (const ulonglong2*)(xh + pb * 1920);
        #pragma unroll
        for (int t = 0; t < 4; ++t) {
            int k4 = xk4s + t;
            ulonglong2 wr = ws4[k4 * 32 + jl];
            ulonglong2 wz = ws4[(96 + k4) * 32 + jl];
            ulonglong2 wn = ws4[(192 + k4) * 32 + jl];
            #pragma unroll
            for (int i = 0; i < 5; ++i) {
                ulonglong2 xv = X[i * 96 + k4];
                ffma2(xr[i], wr.x, xv.x); ffma2(xr[i], wr.y, xv.y);
                ffma2(xz[i], wz.x, xv.x); ffma2(xz[i], wz.y, xv.y);
                ffma2(xn[i], wn.x, xv.x); ffma2(xn[i], wn.y, xv.y);
            }
        }
    };

    stage_x(0, 0);
    __syncthreads();
    compute_xpart(0);

    uint32_t pha[2] = {0, 0};

    for (int s = 0; s < SEQ; ++s) {
        const int p = s & 1;
        const uint32_t mb = mbar_addr + (uint32_t)(p * 8);

        // ---- wait for h(s-1) arrivals (skip s=0: h-section pre-zeroed) ----
        if (s > 0) {
            mbar_wait(mb, pha[p]);
            pha[p] ^= 1;
            if (tid == 0) mbar_expect_tx(mb, HBYTES_PER_STEP);  // next use: s+2
        }

        // ---- h-part gate partials ----
        ull hr[5] = {0,0,0,0,0}, hz[5] = {0,0,0,0,0}, hn[5] = {0,0,0,0,0};
        {
            const ulonglong2* X = (const ulonglong2*)(xh + p * 1920);
            #pragma unroll 2
            for (int t = 0; t < 8; ++t) {
                int k4 = hk4s + t;
                ulonglong2 wr = ws4[k4 * 32 + jl];
                ulonglong2 wz = ws4[(96 + k4) * 32 + jl];
                ulonglong2 wn = ws4[(192 + k4) * 32 + jl];
                #pragma unroll
                for (int i = 0; i < 5; ++i) {
                    ulonglong2 xv = X[i * 96 + k4];
                    ffma2(hr[i], wr.x, xv.x); ffma2(hr[i], wr.y, xv.y);
                    ffma2(hz[i], wz.x, xv.x); ffma2(hz[i], wz.y, xv.y);
                    ffma2(hn[i], wn.x, xv.x); ffma2(hn[i], wn.y, xv.y);
                }
            }
        }
        #pragma unroll
        for (int i = 0; i < 5; ++i) {
            float2 fr = u2f2(hr[i]), fz = u2f2(hz[i]), fh = u2f2(hn[i]);
            float2 gr = u2f2(xr[i]), gz = u2f2(xz[i]), gx = u2f2(xn[i]);
            parts[(w * 5 + i) * 32 + jl] =
                make_float4(fr.x + fr.y + gr.x + gr.y,
                            fz.x + fz.y + gz.x + gz.y,
                            gx.x + gx.y,
                            fh.x + fh.y);
        }
        __syncthreads();

        // ---- reduce 8 warps + GRU elementwise + output ----
        if (tid < 160) {
            int b = tid >> 5, j = tid & 31;
            float4 a = parts[b * 32 + j];
            #pragma unroll
            for (int ww = 1; ww < 8; ++ww) {
                float4 q = parts[(ww * 5 + b) * 32 + j];
                a.x += q.x; a.y += q.y; a.z += q.z; a.w += q.w;
            }
            float r = sigmoidf_fast(a.x);
            float z = sigmoidf_fast(a.y);
            float n = tanhf_fast(a.z + r * a.w);
            float hp = xh[p * 1920 + b * 384 + 128 + j0 + j];
            float h  = fmaf(z, hp - n, n);
            hown[b * 32 + j] = h;
            int bglob = bg * 5 + b;
            if (u == 5)      out[((size_t)s * BATCH + bglob) * 512 + j0 + j] = h;
            else if (u == 6) out[((size_t)s * BATCH + bglob) * 512 + 256 + j0 + j] = h;
            else if (js < 4) g_stage[u][s][bglob][j0 + j] = h;
        }
        __syncthreads();

        // ---- push h(s) to all peers' next buffer via st.async (no barrier) ----
        if (s + 1 < SEQ) {
            uint32_t nxt   = smem_base + XH_OFF + (uint32_t)((p ^ 1) * 7680);
            uint32_t nmbar = mbar_addr + (uint32_t)((p ^ 1) * 8);
            for (int it = tid; it < 320; it += NTH) {
                int peer = it / 40;
                int r2   = it - peer * 40;
                int b = r2 >> 3, j4 = r2 & 7;
                float4 v = hown4[b * 8 + j4];
                uint32_t addr = nxt + (uint32_t)((b * 384 + 128 + j0 + j4 * 4) * 4);
                st_async_f4(addr, nmbar, (uint32_t)peer, v);
            }
        }

        // ---- publish to next unit + stage/compute x-part for s+1 (shadow) ----
        if (u < 5 && js < 4 && tid == 0) {
            __threadfence();
            st_release(&g_flag[u][bg][js][0], s + 1);
        }
        if (s + 1 < SEQ) {
            stage_x(s + 1, p ^ 1);
            __syncthreads();
            compute_xpart(p ^ 1);
        }
    }

    CLUSTER_SYNC();   // no CTA exits while peers' st.async may target it
}

extern "C" __global__ void zero_flags_kernel() {
    int t = threadIdx.x;
    if (t < 5 * 2 * 4 * 8) ((int*)g_flag)[t] = 0;
}

extern "C" void kernel_launch(void* const* d_in, const int* in_sizes, int n_in,
                              void* d_out, int out_size) {
    const float* x         = (const float*)d_in[0];
    const float* w_ih_l0   = (const float*)d_in[1];
    const float* w_ih_rest = (const float*)d_in[2];
    const float* w_hh      = (const float*)d_in[3];
    float* out = (float*)d_out;

    cudaFuncSetAttribute(gru_persistent_kernel,
                         cudaFuncAttributeMaxDynamicSharedMemorySize, SMEM_TOTAL);

    zero_flags_kernel<<<1, 320>>>();
    gru_persistent_kernel<<<112, NTH, SMEM_TOTAL>>>(x, w_ih_l0, w_ih_rest, w_hh, out);
}

// round 4
// speedup vs baseline: 2.1168x; 1.1045x over previous
#include <cuda_runtime.h>
#include <cstdint>

// ----------------------------------------------------------------------------
// Bidirectional 6-layer GRU, SEQ=512, B=10, H=256, I=128.
// 7 live scan units (fwd L0..L5 + bwd L5); bwd L0..L4 are dead code.
// Units 0..5: 2 clusters of 8 CTAs (per batch-group of 5); CTA = 5b x 32j.
// Unit 6 (bwd L5, runs serialized after fwd L4 finishes): 4 clusters of 8
//   (2 bg x 2 bsub); CTA = {3|2}b x 32j -> ~0.6x period during the solo phase.
// Weights SMEM-resident fp32, f32x2 packed FMA.
// h-exchange per step: st.async remote store + mbarrier complete_tx.
// Inter-unit handoff: global staging + release/acquire flags (lag-1).
// ----------------------------------------------------------------------------

#define SEQ    512
#define BATCH  10
#define NTH    256

typedef unsigned long long ull;

__device__ float g_stage[5][SEQ][BATCH][128];
__device__ int   g_flag[5][2][4][8];

// smem layout
#define WS_BYTES    (3*96*32*16)              // 147456 weights ulonglong2[g][k4][j]
#define XH_OFF      WS_BYTES
#define XH_BYTES    (2*5*384*4)               // 15360 xh[2][5][384]
#define PARTS_OFF   (XH_OFF + XH_BYTES)
#define PARTS_BYTES (8*5*32*16)               // 20480 parts[w][b][j] float4
#define HOWN_OFF    (PARTS_OFF + PARTS_BYTES)
#define HOWN_BYTES  (5*32*4)                  // 640
#define MBAR_OFF    (HOWN_OFF + HOWN_BYTES)
#define SMEM_TOTAL  (MBAR_OFF + 16)           // 183968

#define HBYTES_A 5120                         // A-path: 8 peers x 640 B

__device__ __forceinline__ int ld_acquire(const int* p) {
    int v;
    asm volatile("ld.acquire.gpu.b32 %0, [%1];" : "=r"(v) : "l"(p) : "memory");
    return v;
}
__device__ __forceinline__ void st_release(int* p, int v) {
    asm volatile("st.release.gpu.b32 [%0], %1;" :: "l"(p), "r"(v) : "memory");
}
__device__ __forceinline__ void ffma2(ull& d, ull a, ull b) {
    asm volatile("fma.rn.f32x2 %0, %1, %2, %0;" : "+l"(d) : "l"(a), "l"(b));
}
__device__ __forceinline__ float2 u2f2(ull u) {
    float2 f;
    asm("mov.b64 {%0, %1}, %2;" : "=f"(f.x), "=f"(f.y) : "l"(u));
    return f;
}
__device__ __forceinline__ float sigmoidf_fast(float x) {
    return 1.0f / (1.0f + __expf(-x));
}
__device__ __forceinline__ float tanhf_fast(float x) {
    return fmaf(2.0f, 1.0f / (1.0f + __expf(-2.0f * x)), -1.0f);
}
__device__ __forceinline__ uint32_t smem_u32(const void* p) {
    uint32_t a;
    asm("{ .reg .u64 t; cvta.to.shared.u64 t, %1; cvt.u32.u64 %0, t; }"
        : "=r"(a) : "l"(p));
    return a;
}
__device__ __forceinline__ void st_async_f4(uint32_t laddr, uint32_t lmbar,
                                            uint32_t rank, float4 v) {
    asm volatile(
        "{\n\t.reg .b32 ra, rm;\n\t"
        "mapa.shared::cluster.u32 ra, %0, %2;\n\t"
        "mapa.shared::cluster.u32 rm, %1, %2;\n\t"
        "st.async.shared::cluster.mbarrier::complete_tx::bytes.v4.f32 "
        "[ra], {%3, %4, %5, %6}, [rm];\n\t}"
        :: "r"(laddr), "r"(lmbar), "r"(rank),
           "f"(v.x), "f"(v.y), "f"(v.z), "f"(v.w)
        : "memory");
}
__device__ __forceinline__ void mbar_init(uint32_t mbar, uint32_t cnt) {
    asm volatile("mbarrier.init.shared.b64 [%0], %1;" :: "r"(mbar), "r"(cnt) : "memory");
}
__device__ __forceinline__ void mbar_expect_tx(uint32_t mbar, uint32_t bytes) {
    asm volatile("mbarrier.arrive.expect_tx.shared.b64 _, [%0], %1;"
                 :: "r"(mbar), "r"(bytes) : "memory");
}
__device__ __forceinline__ void mbar_wait(uint32_t mbar, uint32_t parity) {
    asm volatile(
        "{\n\t.reg .pred P;\n\t"
        "LWAIT_%=:\n\t"
        "mbarrier.try_wait.parity.acquire.cluster.shared::cta.b64 P, [%0], %1, 0x989680;\n\t"
        "@!P bra LWAIT_%=;\n\t}"
        :: "r"(mbar), "r"(parity) : "memory");
}
#define CLUSTER_SYNC() do { \
    asm volatile("barrier.cluster.arrive.aligned;" ::: "memory"); \
    asm volatile("barrier.cluster.wait.aligned;"   ::: "memory"); \
} while (0)

// ============================ unit-6 scan loop ==============================
// CTA = NB batches (boff within bg) x 32 j. Cluster = 8 j-slices, same batches.
template<int NB>
__device__ __forceinline__ void u6_loop(float* __restrict__ out,
                                        char* smem, uint32_t smem_base,
                                        int bg, int boff, int js, int tid)
{
    ulonglong2* ws4   = (ulonglong2*)smem;
    float*      xh    = (float*)(smem + XH_OFF);
    float4*     parts = (float4*)(smem + PARTS_OFF);
    float*      hown  = (float*)(smem + HOWN_OFF);
    float4*     hown4 = (float4*)(smem + HOWN_OFF);
    const uint32_t mbar_addr = smem_base + MBAR_OFF;
    const int j0 = js * 32;
    const int exp_tx = NB * 1024;   // 8 peers x NB*32*4 B

    // zero h-section of buffer 0
    for (int t = tid; t < NB * 64; t += NTH) {
        int b = t >> 6, q = t & 63;
        *(float4*)&xh[b * 384 + 128 + q * 4] = make_float4(0.f, 0.f, 0.f, 0.f);
    }
    if (tid == 0) {
        mbar_init(mbar_addr, 1);
        mbar_init(mbar_addr + 8, 1);
        mbar_expect_tx(mbar_addr,     exp_tx);
        mbar_expect_tx(mbar_addr + 8, exp_tx);
    }
    __syncthreads();
    CLUSTER_SYNC();

    auto stage_x = [&](int sn, int pb) {
        float* dst = xh + pb * 1920;
        int ss   = SEQ - 1 - sn;
        int need = SEQ - sn;
        if (tid < 4) {
            const int* fp = &g_flag[4][bg][tid][0];
            while (ld_acquire(fp) < need) __nanosleep(128);
        }
        __syncthreads();
        const float* src = &g_stage[4][ss][bg * 5 + boff][0];
        for (int t = tid; t < NB * 32; t += NTH) {
            int b = t >> 5, q = t & 31;
            *(float4*)&dst[b * 384 + q * 4] = *(const float4*)&src[b * 128 + q * 4];
        }
    };

    const int w  = tid >> 5;
    const int jl = tid & 31;
    const int xk4s = w * 4;
    const int hk4s = 32 + w * 8;

    ull xr[NB], xz[NB], xn[NB];
    auto compute_xpart = [&](int pb) {
        #pragma unroll
        for (int i = 0; i < NB; ++i) { xr[i] = 0; xz[i] = 0; xn[i] = 0; }
        const ulonglong2* X = (const ulonglong2*)(xh + pb * 1920);
        #pragma unroll
        for (int t = 0; t < 4; ++t) {
            int k4 = xk4s + t;
            ulonglong2 wr = ws4[k4 * 32 + jl];
            ulonglong2 wz = ws4[(96 + k4) * 32 + jl];
            ulonglong2 wn = ws4[(192 + k4) * 32 + jl];
            #pragma unroll
            for (int i = 0; i < NB; ++i) {
                ulonglong2 xv = X[i * 96 + k4];
                ffma2(xr[i], wr.x, xv.x); ffma2(xr[i], wr.y, xv.y);
                ffma2(xz[i], wz.x, xv.x); ffma2(xz[i], wz.y, xv.y);
                ffma2(xn[i], wn.x, xv.x); ffma2(xn[i], wn.y, xv.y);
            }
        }
    };

    stage_x(0, 0);
    __syncthreads();
    compute_xpart(0);

    uint32_t pha[2] = {0, 0};

    for (int s = 0; s < SEQ; ++s) {
        const int p = s & 1;
        const uint32_t mb = mbar_addr + (uint32_t)(p * 8);

        if (s > 0) {
            mbar_wait(mb, pha[p]);
            pha[p] ^= 1;
            if (tid == 0) mbar_expect_tx(mb, exp_tx);
        }

        ull hr[NB], hz[NB], hn[NB];
        #pragma unroll
        for (int i = 0; i < NB; ++i) { hr[i] = 0; hz[i] = 0; hn[i] = 0; }
        {
            const ulonglong2* X = (const ulonglong2*)(xh + p * 1920);
            #pragma unroll 2
            for (int t = 0; t < 8; ++t) {
                int k4 = hk4s + t;
                ulonglong2 wr = ws4[k4 * 32 + jl];
                ulonglong2 wz = ws4[(96 + k4) * 32 + jl];
                ulonglong2 wn = ws4[(192 + k4) * 32 + jl];
                #pragma unroll
                for (int i = 0; i < NB; ++i) {
                    ulonglong2 xv = X[i * 96 + k4];
                    ffma2(hr[i], wr.x, xv.x); ffma2(hr[i], wr.y, xv.y);
                    ffma2(hz[i], wz.x, xv.x); ffma2(hz[i], wz.y, xv.y);
                    ffma2(hn[i], wn.x, xv.x); ffma2(hn[i], wn.y, xv.y);
                }
            }
        }
        #pragma unroll
        for (int i = 0; i < NB; ++i) {
            float2 fr = u2f2(hr[i]), fz = u2f2(hz[i]), fh = u2f2(hn[i]);
            float2 gr = u2f2(xr[i]), gz = u2f2(xz[i]), gx = u2f2(xn[i]);
            parts[(w * NB + i) * 32 + jl] =
                make_float4(fr.x + fr.y + gr.x + gr.y,
                            fz.x + fz.y + gz.x + gz.y,
                            gx.x + gx.y,
                            fh.x + fh.y);
        }
        __syncthreads();

        if (tid < NB * 32) {
            int b = tid >> 5, j = tid & 31;
            float4 a = parts[b * 32 + j];
            #pragma unroll
            for (int ww = 1; ww < 8; ++ww) {
                float4 q = parts[(ww * NB + b) * 32 + j];
                a.x += q.x; a.y += q.y; a.z += q.z; a.w += q.w;
            }
            float r = sigmoidf_fast(a.x);
            float z = sigmoidf_fast(a.y);
            float n = tanhf_fast(a.z + r * a.w);
            float hp = xh[p * 1920 + b * 384 + 128 + j0 + j];
            float h  = fmaf(z, hp - n, n);
            hown[b * 32 + j] = h;
            int bglob = bg * 5 + boff + b;
            out[((size_t)s * BATCH + bglob) * 512 + 256 + j0 + j] = h;
        }
        __syncthreads();

        if (s + 1 < SEQ) {
            uint32_t nxt   = smem_base + XH_OFF + (uint32_t)((p ^ 1) * 7680);
            uint32_t nmbar = mbar_addr + (uint32_t)((p ^ 1) * 8);
            for (int it = tid; it < NB * 64; it += NTH) {
                int peer = it / (NB * 8);
                int r2   = it - peer * (NB * 8);
                int b = r2 >> 3, j4 = r2 & 7;
                float4 v = hown4[b * 8 + j4];
                uint32_t addr = nxt + (uint32_t)((b * 384 + 128 + j0 + j4 * 4) * 4);
                st_async_f4(addr, nmbar, (uint32_t)peer, v);
            }
            stage_x(s + 1, p ^ 1);
            __syncthreads();
            compute_xpart(p ^ 1);
        }
    }
}

// ================================ kernel ====================================
extern "C" __global__ void __launch_bounds__(NTH, 1) __cluster_dims__(8, 1, 1)
gru_persistent_kernel(const float* __restrict__ x,
                      const float* __restrict__ w_ih_l0,
                      const float* __restrict__ w_ih_rest,
                      const float* __restrict__ w_hh,
                      float* __restrict__ out)
{
    extern __shared__ char smem[];
    ulonglong2* ws4   = (ulonglong2*)smem;
    float*      xh    = (float*)(smem + XH_OFF);
    float4*     parts = (float4*)(smem + PARTS_OFF);
    float*      hown  = (float*)(smem + HOWN_OFF);
    float4*     hown4 = (float4*)(smem + HOWN_OFF);
    const uint32_t smem_base = smem_u32(smem);
    const uint32_t mbar_addr = smem_base + MBAR_OFF;

    const int cta = blockIdx.x;
    const int tid = threadIdx.x;
    const bool isA = (cta < 96);

    // unit/shape decode
    int u, bg, js, boff, nb;
    if (isA) {
        u  = cta >> 4;            // 0..5
        bg = (cta >> 3) & 1;
        js = cta & 7;
        boff = 0; nb = 5;
    } else {
        int t = cta - 96;         // unit 6: 2bg x 2bsub x 8js
        u  = 6;
        bg = t >> 4;
        int bsub = (t >> 3) & 1;
        js = t & 7;
        boff = bsub ? 3 : 0;
        nb = bsub ? 2 : 3;
    }
    const int j0 = js * 32;
    const int layer = (u < 6) ? u : 5;
    const int dir   = (u == 6) ? 1 : 0;
    const int src_u = u - 1;      // A-path only (u>=1)

    // -------- weights -> smem: ws4[g][k4][j] --------
    const float* Whh = w_hh + (size_t)(layer * 2 + dir) * 768 * 256;
    const float* Wih;
    int pitch;
    if (layer == 0) { Wih = w_ih_l0 + (size_t)dir * 768 * 128; pitch = 128; }
    else            { Wih = w_ih_rest + (size_t)((layer - 1) * 2 + dir) * 768 * 512; pitch = 512; }

    for (int idx = tid; idx < 3 * 96 * 32; idx += NTH) {
        int j  = idx & 31;
        int k4 = (idx >> 5) % 96;
        int g  = idx / (96 * 32);
        int row = g * 256 + j0 + j;
        int k   = k4 * 4;
        const float* src = (k < 128) ? (Wih + (size_t)row * pitch + k)
                                     : (Whh + (size_t)row * 256 + (k - 128));
        ((float4*)ws4)[idx] = *(const float4*)src;
    }
    __syncthreads();

    if (!isA) {
        if (nb == 3) u6_loop<3>(out, smem, smem_base, bg, boff, js, tid);
        else         u6_loop<2>(out, smem, smem_base, bg, boff, js, tid);
        CLUSTER_SYNC();
        return;
    }

    // ============================ A-path (units 0..5) =======================
    for (int t = tid; t < 320; t += NTH) {
        int b = t >> 6, q = t & 63;
        *(float4*)&xh[b * 384 + 128 + q * 4] = make_float4(0.f, 0.f, 0.f, 0.f);
    }
    if (tid == 0) {
        mbar_init(mbar_addr, 1);
        mbar_init(mbar_addr + 8, 1);
        mbar_expect_tx(mbar_addr,     HBYTES_A);
        mbar_expect_tx(mbar_addr + 8, HBYTES_A);
    }
    __syncthreads();
    CLUSTER_SYNC();

    auto stage_x = [&](int sn, int pb) {
        float* dst = xh + pb * 1920;
        if (u == 0) {
            const float* src = x + ((size_t)sn * BATCH + bg * 5) * 128;
            for (int t = tid; t < 160; t += NTH) {
                int b = t >> 5, q = t & 31;
                *(float4*)&dst[b * 384 + q * 4] = *(const float4*)&src[b * 128 + q * 4];
            }
        } else {
            if (tid < 4) {
                const int* fp = &g_flag[src_u][bg][tid][0];
                while (ld_acquire(fp) < sn + 1) __nanosleep(128);
            }
            __syncthreads();
            const float* src = &g_stage[src_u][sn][bg * 5][0];
            for (int t = tid; t < 160; t += NTH) {
                int b = t >> 5, q = t & 31;
                *(float4*)&dst[b * 384 + q * 4] = *(const float4*)&src[b * 128 + q * 4];
            }
        }
    };

    const int w  = tid >> 5;
    const int jl = tid & 31;
    const int xk4s = w * 4;
    const int hk4s = 32 + w * 8;

    ull xr[5], xz[5], xn[5];
    auto compute_xpart = [&](int pb) {
        #pragma unroll
        for (int i = 0; i < 5; ++i) { xr[i] = 0; xz[i] = 0; xn[i] = 0; }
        const ulonglong2* X = (const ulonglong2*)(xh + pb * 1920);
        #pragma unroll
        for (int t = 0; t < 4; ++t) {
            int k4 = xk4s + t;
            ulonglong2 wr = ws4[k4 * 32 + jl];
            ulonglong2 wz = ws4[(96 + k4) * 32 + jl];
            ulonglong2 wn = ws4[(192 + k4) * 32 + jl];
            #pragma unroll
            for (int i = 0; i < 5; ++i) {
                ulonglong2 xv = X[i * 96 + k4];
                ffma2(xr[i], wr.x, xv.x); ffma2(xr[i], wr.y, xv.y);
                ffma2(xz[i], wz.x, xv.x); ffma2(xz[i], wz.y, xv.y);
                ffma2(xn[i], wn.x, xv.x); ffma2(xn[i], wn.y, xv.y);
            }
        }
    };

    stage_x(0, 0);
    __syncthreads();
    compute_xpart(0);

    uint32_t pha[2] = {0, 0};

    for (int s = 0; s < SEQ; ++s) {
        const int p = s & 1;
        const uint32_t mb = mbar_addr + (uint32_t)(p * 8);

        if (s > 0) {
            mbar_wait(mb, pha[p]);
            pha[p] ^= 1;
            if (tid == 0) mbar_expect_tx(mb, HBYTES_A);
        }

        ull hr[5] = {0,0,0,0,0}, hz[5] = {0,0,0,0,0}, hn[5] = {0,0,0,0,0};
        {
            const ulonglong2* X = (const ulonglong2*)(xh + p * 1920);
            #pragma unroll 2
            for (int t = 0; t < 8; ++t) {
                int k4 = hk4s + t;
                ulonglong2 wr = ws4[k4 * 32 + jl];
                ulonglong2 wz = ws4[(96 + k4) * 32 + jl];
                ulonglong2 wn = ws4[(192 + k4) * 32 + jl];
                #pragma unroll
                for (int i = 0; i < 5; ++i) {
                    ulonglong2 xv = X[i * 96 + k4];
                    ffma2(hr[i], wr.x, xv.x); ffma2(hr[i], wr.y, xv.y);
                    ffma2(hz[i], wz.x, xv.x); ffma2(hz[i], wz.y, xv.y);
                    ffma2(hn[i], wn.x, xv.x); ffma2(hn[i], wn.y, xv.y);
                }
            }
        }
        #pragma unroll
        for (int i = 0; i < 5; ++i) {
            float2 fr = u2f2(hr[i]), fz = u2f2(hz[i]), fh = u2f2(hn[i]);
            float2 gr = u2f2(xr[i]), gz = u2f2(xz[i]), gx = u2f2(xn[i]);
            parts[(w * 5 + i) * 32 + jl] =
                make_float4(fr.x + fr.y + gr.x + gr.y,
                            fz.x + fz.y + gz.x + gz.y,
                            gx.x + gx.y,
                            fh.x + fh.y);
        }
        __syncthreads();

        if (tid < 160) {
            int b = tid >> 5, j = tid & 31;
            float4 a = parts[b * 32 + j];
            #pragma unroll
            for (int ww = 1; ww < 8; ++ww) {
                float4 q = parts[(ww * 5 + b) * 32 + j];
                a.x += q.x; a.y += q.y; a.z += q.z; a.w += q.w;
            }
            float r = sigmoidf_fast(a.x);
            float z = sigmoidf_fast(a.y);
            float n = tanhf_fast(a.z + r * a.w);
            float hp = xh[p * 1920 + b * 384 + 128 + j0 + j];
            float h  = fmaf(z, hp - n, n);
            hown[b * 32 + j] = h;
            int bglob = bg * 5 + b;
            if (u == 5)      out[((size_t)s * BATCH + bglob) * 512 + j0 + j] = h;
            else if (js < 4) g_stage[u][s][bglob][j0 + j] = h;
        }
        __syncthreads();

        if (s + 1 < SEQ) {
            uint32_t nxt   = smem_base + XH_OFF + (uint32_t)((p ^ 1) * 7680);
            uint32_t nmbar = mbar_addr + (uint32_t)((p ^ 1) * 8);
            for (int it = tid; it < 320; it += NTH) {
                int peer = it / 40;
                int r2   = it - peer * 40;
                int b = r2 >> 3, j4 = r2 & 7;
                float4 v = hown4[b * 8 + j4];
                uint32_t addr = nxt + (uint32_t)((b * 384 + 128 + j0 + j4 * 4) * 4);
                st_async_f4(addr, nmbar, (uint32_t)peer, v);
            }
        }

        if (u < 5 && js < 4 && tid == 0) {
            __threadfence();
            st_release(&g_flag[u][bg][js][0], s + 1);
        }
        if (s + 1 < SEQ) {
            stage_x(s + 1, p ^ 1);
            __syncthreads();
            compute_xpart(p ^ 1);
        }
    }

    CLUSTER_SYNC();
}

extern "C" __global__ void zero_flags_kernel() {
    int t = threadIdx.x;
    if (t < 5 * 2 * 4 * 8) ((int*)g_flag)[t] = 0;
}

extern "C" void kernel_launch(void* const* d_in, const int* in_sizes, int n_in,
                              void* d_out, int out_size) {
    const float* x         = (const float*)d_in[0];
    const float* w_ih_l0   = (const float*)d_in[1];
    const float* w_ih_rest = (const float*)d_in[2];
    const float* w_hh      = (const float*)d_in[3];
    float* out = (float*)d_out;

    cudaFuncSetAttribute(gru_persistent_kernel,
                         cudaFuncAttributeMaxDynamicSharedMemorySize, SMEM_TOTAL);

    zero_flags_kernel<<<1, 320>>>();
    gru_persistent_kernel<<<128, NTH, SMEM_TOTAL>>>(x, w_ih_l0, w_ih_rest, w_hh, out);
}

// round 5
// speedup vs baseline: 2.6107x; 1.2333x over previous
#include <cuda_runtime.h>
#include <cstdint>

// ----------------------------------------------------------------------------
// Bidirectional 6-layer GRU, SEQ=512, B=10, H=256, I=128.
// 7 live scan units (fwd L0..L5 + bwd L5); bwd L0..L4 are dead code.
// Units 0..5: 2 clusters of 8 (batch-groups of 5), CTA = 5b x 32j.
// Unit 6:     4 clusters of 8 (2bg x 2bsub),       CTA = {3|2}b x 32j.
// Weights SMEM-resident fp32, f32x2 packed FMA.
// Per-peer mbarriers: warp w consumes exactly peer w's 32-j h-slice, so it
// waits only on mbar[buf][w] (fine-grained producer->consumer, no CTA-wide
// rendezvous). Reduce threads push h directly after __syncwarp; stage warps
// (5-7) poll inter-unit flags + stage x(s+1) in parallel. mapa hoisted.
// ----------------------------------------------------------------------------

#define SEQ    512
#define BATCH  10
#define NTH    256

typedef unsigned long long ull;

__device__ float g_stage[5][SEQ][BATCH][128];
__device__ int   g_flag[5][2][4][8];

// smem layout
#define WS_BYTES    (3*96*32*16)              // 147456 weights ulonglong2[g][k4][j]
#define XH_OFF      WS_BYTES
#define XH_BYTES    (2*5*384*4)               // 15360 xh[2][5][384]
#define PARTS_OFF   (XH_OFF + XH_BYTES)
#define PARTS_BYTES (8*5*32*16)               // 20480 parts[w][b][j] float4
#define HOWN_OFF    (PARTS_OFF + PARTS_BYTES)
#define HOWN_BYTES  (5*32*4)                  // 640
#define MBAR_OFF    (HOWN_OFF + HOWN_BYTES)   // 16 mbars: [buf][peer]
#define SMEM_TOTAL  (MBAR_OFF + 128)
#define MBAR_DELTA  (MBAR_OFF - XH_OFF)

__device__ __forceinline__ int ld_acquire(const int* p) {
    int v;
    asm volatile("ld.acquire.gpu.b32 %0, [%1];" : "=r"(v) : "l"(p) : "memory");
    return v;
}
__device__ __forceinline__ void st_release(int* p, int v) {
    asm volatile("st.release.gpu.b32 [%0], %1;" :: "l"(p), "r"(v) : "memory");
}
__device__ __forceinline__ void ffma2(ull& d, ull a, ull b) {
    asm volatile("fma.rn.f32x2 %0, %1, %2, %0;" : "+l"(d) : "l"(a), "l"(b));
}
__device__ __forceinline__ float2 u2f2(ull u) {
    float2 f;
    asm("mov.b64 {%0, %1}, %2;" : "=f"(f.x), "=f"(f.y) : "l"(u));
    return f;
}
__device__ __forceinline__ float sigmoidf_fast(float x) {
    return 1.0f / (1.0f + __expf(-x));
}
__device__ __forceinline__ float tanhf_fast(float x) {
    return fmaf(2.0f, 1.0f / (1.0f + __expf(-2.0f * x)), -1.0f);
}
__device__ __forceinline__ uint32_t smem_u32(const void* p) {
    uint32_t a;
    asm("{ .reg .u64 t; cvta.to.shared.u64 t, %1; cvt.u32.u64 %0, t; }"
        : "=r"(a) : "l"(p));
    return a;
}
__device__ __forceinline__ uint32_t mapa_u32(uint32_t laddr, uint32_t rank) {
    uint32_t r;
    asm("mapa.shared::cluster.u32 %0, %1, %2;" : "=r"(r) : "r"(laddr), "r"(rank));
    return r;
}
// st.async with precomputed remote addresses (no mapa in hot path)
__device__ __forceinline__ void st_async_f4_pre(uint32_t raddr, uint32_t rmbar,
                                                float4 v) {
    asm volatile(
        "st.async.shared::cluster.mbarrier::complete_tx::bytes.v4.f32 "
        "[%0], {%2, %3, %4, %5}, [%1];"
        :: "r"(raddr), "r"(rmbar), "f"(v.x), "f"(v.y), "f"(v.z), "f"(v.w)
        : "memory");
}
__device__ __forceinline__ void mbar_init(uint32_t mbar, uint32_t cnt) {
    asm volatile("mbarrier.init.shared.b64 [%0], %1;" :: "r"(mbar), "r"(cnt) : "memory");
}
__device__ __forceinline__ void mbar_expect_tx(uint32_t mbar, uint32_t bytes) {
    asm volatile("mbarrier.arrive.expect_tx.shared.b64 _, [%0], %1;"
                 :: "r"(mbar), "r"(bytes) : "memory");
}
__device__ __forceinline__ void mbar_wait(uint32_t mbar, uint32_t parity) {
    asm volatile(
        "{\n\t.reg .pred P;\n\t"
        "LWAIT_%=:\n\t"
        "mbarrier.try_wait.parity.acquire.cluster.shared::cta.b64 P, [%0], %1, 0x989680;\n\t"
        "@!P bra LWAIT_%=;\n\t}"
        :: "r"(mbar), "r"(parity) : "memory");
}
#define CLUSTER_SYNC() do { \
    asm volatile("barrier.cluster.arrive.aligned;" ::: "memory"); \
    asm volatile("barrier.cluster.wait.aligned;"   ::: "memory"); \
} while (0)
#define BAR_STAGE() asm volatile("bar.sync 1, 96;" ::: "memory")

// ============================= unified scan loop ============================
// MODE: 0 = fwd hidden layer (write g_stage), 1 = fwd L5 (out left),
//       2 = bwd L5 (out right, reversed input).
template<int NB, int MODE>
__device__ __forceinline__ void scan_loop(
    const float* __restrict__ x, float* __restrict__ out,
    char* smem, uint32_t smem_base,
    int u, int bg, int boff, int js, int tid)
{
    ulonglong2* ws4   = (ulonglong2*)smem;
    float*      xh    = (float*)(smem + XH_OFF);
    float4*     parts = (float4*)(smem + PARTS_OFF);
    float*      hown  = (float*)(smem + HOWN_OFF);
    float4*     hown4 = (float4*)(smem + HOWN_OFF);
    const uint32_t mbar_base = smem_base + MBAR_OFF;
    const int j0 = js * 32;
    const uint32_t exp_tx = NB * 128;
    const int src_u = (MODE == 2) ? 4 : (u - 1);

    // precompute remote xh bases for all 8 peers (mapa hoisted out of loop)
    uint32_t rxh[8];
    #pragma unroll
    for (int pe = 0; pe < 8; ++pe)
        rxh[pe] = mapa_u32(smem_base + XH_OFF, (uint32_t)pe);

    // zero h-section of buffer 0
    for (int t = tid; t < NB * 64; t += NTH) {
        int b = t >> 6, q = t & 63;
        *(float4*)&xh[b * 384 + 128 + q * 4] = make_float4(0.f, 0.f, 0.f, 0.f);
    }
    if (tid < 16) {
        mbar_init(mbar_base + tid * 8, 1);
        mbar_expect_tx(mbar_base + tid * 8, exp_tx);
    }
    __syncthreads();
    CLUSTER_SYNC();

    // stage x(sn) into buffer pb — executed by warps 5..7 only (96 threads)
    auto stage_x = [&](int sn, int pb) {
        float* dst = xh + pb * 1920;
        if (MODE == 0 && u == 0) {
            const float* src = x + ((size_t)sn * BATCH + bg * 5 + boff) * 128;
            for (int t = tid - 160; t < NB * 32; t += 96) {
                int b = t >> 5, q = t & 31;
                *(float4*)&dst[b * 384 + q * 4] = *(const float4*)&src[b * 128 + q * 4];
            }
        } else {
            int ss   = (MODE == 2) ? (SEQ - 1 - sn) : sn;
            int need = (MODE == 2) ? (SEQ - sn) : (sn + 1);
            if (tid >= 224 && tid < 228) {
                const int* fp = &g_flag[src_u][bg][tid - 224][0];
                while (ld_acquire(fp) < need) __nanosleep(128);
            }
            BAR_STAGE();
            const float* src = &g_stage[src_u][ss][bg * 5 + boff][0];
            for (int t = tid - 160; t < NB * 32; t += 96) {
                int b = t >> 5, q = t & 31;
                *(float4*)&dst[b * 384 + q * 4] = *(const float4*)&src[b * 128 + q * 4];
            }
        }
    };

    const int w  = tid >> 5;
    const int jl = tid & 31;
    const int xk4s = w * 4;
    const int hk4s = 32 + w * 8;
    const uint32_t my_mb0 = mbar_base + (uint32_t)(w * 8);   // [buf0][w]

    ull xr[NB], xz[NB], xn[NB];
    auto compute_xpart = [&](int pb) {
        #pragma unroll
        for (int i = 0; i < NB; ++i) { xr[i] = 0; xz[i] = 0; xn[i] = 0; }
        const ulonglong2* X = (const ulonglong2*)(xh + pb * 1920);
        #pragma unroll
        for (int t = 0; t < 4; ++t) {
            int k4 = xk4s + t;
            ulonglong2 wr = ws4[k4 * 32 + jl];
            ulonglong2 wz = ws4[(96 + k4) * 32 + jl];
            ulonglong2 wn = ws4[(192 + k4) * 32 + jl];
            #pragma unroll
            for (int i = 0; i < NB; ++i) {
                ulonglong2 xv = X[i * 96 + k4];
                ffma2(xr[i], wr.x, xv.x); ffma2(xr[i], wr.y, xv.y);
                ffma2(xz[i], wz.x, xv.x); ffma2(xz[i], wz.y, xv.y);
                ffma2(xn[i], wn.x, xv.x); ffma2(xn[i], wn.y, xv.y);
            }
        }
    };

    if (tid >= 160) stage_x(0, 0);
    __syncthreads();
    compute_xpart(0);

    uint32_t pha[2] = {0, 0};

    for (int s = 0; s < SEQ; ++s) {
        const int p = s & 1;

        // prefetch iteration-0 weights (independent of the barrier)
        ulonglong2 wr0 = ws4[hk4s * 32 + jl];
        ulonglong2 wz0 = ws4[(96 + hk4s) * 32 + jl];
        ulonglong2 wn0 = ws4[(192 + hk4s) * 32 + jl];

        // ---- per-warp wait: only peer w's slice feeds this warp's k4 range ----
        if (s > 0) {
            uint32_t mb = my_mb0 + (uint32_t)(p * 64);
            mbar_wait(mb, pha[p]);
            pha[p] ^= 1;
            if (jl == 0) mbar_expect_tx(mb, exp_tx);
        }

        // ---- h-part gate partials ----
        ull hr[NB], hz[NB], hn[NB];
        #pragma unroll
        for (int i = 0; i < NB; ++i) { hr[i] = 0; hz[i] = 0; hn[i] = 0; }
        const ulonglong2* X = (const ulonglong2*)(xh + p * 1920);
        #pragma unroll
        for (int i = 0; i < NB; ++i) {
            ulonglong2 xv = X[i * 96 + hk4s];
            ffma2(hr[i], wr0.x, xv.x); ffma2(hr[i], wr0.y, xv.y);
            ffma2(hz[i], wz0.x, xv.x); ffma2(hz[i], wz0.y, xv.y);
            ffma2(hn[i], wn0.x, xv.x); ffma2(hn[i], wn0.y, xv.y);
        }
        #pragma unroll 2
        for (int t = 1; t < 8; ++t) {
            int k4 = hk4s + t;
            ulonglong2 wr = ws4[k4 * 32 + jl];
            ulonglong2 wz = ws4[(96 + k4) * 32 + jl];
            ulonglong2 wn = ws4[(192 + k4) * 32 + jl];
            #pragma unroll
            for (int i = 0; i < NB; ++i) {
                ulonglong2 xv = X[i * 96 + k4];
                ffma2(hr[i], wr.x, xv.x); ffma2(hr[i], wr.y, xv.y);
                ffma2(hz[i], wz.x, xv.x); ffma2(hz[i], wz.y, xv.y);
                ffma2(hn[i], wn.x, xv.x); ffma2(hn[i], wn.y, xv.y);
            }
        }
        #pragma unroll
        for (int i = 0; i < NB; ++i) {
            float2 fr = u2f2(hr[i]), fz = u2f2(hz[i]), fh = u2f2(hn[i]);
            float2 gr = u2f2(xr[i]), gz = u2f2(xz[i]), gx = u2f2(xn[i]);
            parts[(w * NB + i) * 32 + jl] =
                make_float4(fr.x + fr.y + gr.x + gr.y,
                            fz.x + fz.y + gz.x + gz.y,
                            gx.x + gx.y,
                            fh.x + fh.y);
        }
        __syncthreads();   // sync #1: all partials in smem

        // ---- warps 0..NB-1: reduce + GRU elementwise + push; warps 5-7: stage ----
        if (tid < NB * 32) {
            int b = tid >> 5, j = tid & 31;
            float4 a = parts[b * 32 + j];
            #pragma unroll
            for (int ww = 1; ww < 8; ++ww) {
                float4 q = parts[(ww * NB + b) * 32 + j];
                a.x += q.x; a.y += q.y; a.z += q.z; a.w += q.w;
            }
            float r = sigmoidf_fast(a.x);
            float z = sigmoidf_fast(a.y);
            float n = tanhf_fast(a.z + r * a.w);
            float hp = xh[p * 1920 + b * 384 + 128 + j0 + j];
            float h  = fmaf(z, hp - n, n);
            hown[b * 32 + j] = h;
            int bglob = bg * 5 + boff + b;
            if (MODE == 1)      out[((size_t)s * BATCH + bglob) * 512 + j0 + j] = h;
            else if (MODE == 2) out[((size_t)s * BATCH + bglob) * 512 + 256 + j0 + j] = h;
            else if (js < 4)    g_stage[u][s][bglob][j0 + j] = h;
            __syncwarp();
            // push own slice to all 8 peers (incl. self) into buffer p^1
            if ((j & 3) == 0 && s + 1 < SEQ) {
                float4 v = hown4[b * 8 + (j >> 2)];
                uint32_t off  = (uint32_t)(((p ^ 1) * 1920 + b * 384 + 128 + j0 + j) * 4);
                uint32_t moff = (uint32_t)(MBAR_DELTA + (p ^ 1) * 64 + js * 8);
                #pragma unroll
                for (int pe = 0; pe < 8; ++pe)
                    st_async_f4_pre(rxh[pe] + off, rxh[pe] + moff, v);
            }
        } else if (tid >= 160 && s + 1 < SEQ) {
            stage_x(s + 1, p ^ 1);
        }
        __syncthreads();   // sync #2: staged x visible; parts free for reuse

        if (MODE == 0 && js < 4 && tid == 0) {
            __threadfence();
            st_release(&g_flag[u][bg][js][0], s + 1);
        }
        if (s + 1 < SEQ) compute_xpart(p ^ 1);
    }
}

// ================================ kernel ====================================
extern "C" __global__ void __launch_bounds__(NTH, 1) __cluster_dims__(8, 1, 1)
gru_persistent_kernel(const float* __restrict__ x,
                      const float* __restrict__ w_ih_l0,
                      const float* __restrict__ w_ih_rest,
                      const float* __restrict__ w_hh,
                      float* __restrict__ out)
{
    extern __shared__ char smem[];
    const uint32_t smem_base = smem_u32(smem);
    const int cta = blockIdx.x;
    const int tid = threadIdx.x;
    const bool isA = (cta < 96);

    int u, bg, js, boff, nb;
    if (isA) {
        u  = cta >> 4;            // 0..5
        bg = (cta >> 3) & 1;
        js = cta & 7;
        boff = 0; nb = 5;
    } else {
        int t = cta - 96;         // unit 6: 2bg x 2bsub x 8js
        u  = 6;
        bg = t >> 4;
        int bsub = (t >> 3) & 1;
        js = t & 7;
        boff = bsub ? 3 : 0;
        nb = bsub ? 2 : 3;
    }
    const int j0 = js * 32;
    const int layer = (u < 6) ? u : 5;
    const int dir   = (u == 6) ? 1 : 0;

    // -------- weights -> smem: ws4[g][k4][j] --------
    const float* Whh = w_hh + (size_t)(layer * 2 + dir) * 768 * 256;
    const float* Wih;
    int pitch;
    if (layer == 0) { Wih = w_ih_l0 + (size_t)dir * 768 * 128; pitch = 128; }
    else            { Wih = w_ih_rest + (size_t)((layer - 1) * 2 + dir) * 768 * 512; pitch = 512; }

    for (int idx = tid; idx < 3 * 96 * 32; idx += NTH) {
        int j  = idx & 31;
        int k4 = (idx >> 5) % 96;
        int g  = idx / (96 * 32);
        int row = g * 256 + j0 + j;
        int k   = k4 * 4;
        const float* src = (k < 128) ? (Wih + (size_t)row * pitch + k)
                                     : (Whh + (size_t)row * 256 + (k - 128));
        ((float4*)smem)[idx] = *(const float4*)src;
    }
    __syncthreads();

    if (isA) {
        if (u < 5) scan_loop<5, 0>(x, out, smem, smem_base, u, bg, boff, js, tid);
        else       scan_loop<5, 1>(x, out, smem, smem_base, u, bg, boff, js, tid);
    } else {
        if (nb == 3) scan_loop<3, 2>(x, out, smem, smem_base, u, bg, boff, js, tid);
        else         scan_loop<2, 2>(x, out, smem, smem_base, u, bg, boff, js, tid);
    }

    CLUSTER_SYNC();
}

extern "C" __global__ void zero_flags_kernel() {
    int t = threadIdx.x;
    if (t < 5 * 2 * 4 * 8) ((int*)g_flag)[t] = 0;
}

extern "C" void kernel_launch(void* const* d_in, const int* in_sizes, int n_in,
                              void* d_out, int out_size) {
    const float* x         = (const float*)d_in[0];
    const float* w_ih_l0   = (const float*)d_in[1];
    const float* w_ih_rest = (const float*)d_in[2];
    const float* w_hh      = (const float*)d_in[3];
    float* out = (float*)d_out;

    cudaFuncSetAttribute(gru_persistent_kernel,
                         cudaFuncAttributeMaxDynamicSharedMemorySize, SMEM_TOTAL);

    zero_flags_kernel<<<1, 320>>>();
    gru_persistent_kernel<<<128, NTH, SMEM_TOTAL>>>(x, w_ih_l0, w_ih_rest, w_hh, out);
}